// round 9
// baseline (speedup 1.0000x reference)
#include <cuda_runtime.h>
#include <math.h>
#include <float.h>

// LSH attention: B=16, S=4096, D=64, H=8 hashes, bucket_size=64
#define BB 16
#define SS 4096
#define DD 64
#define HH 8
#define NBK 64          // n_buckets
#define CPB 512         // chunks per batch = H * n_buckets
#define TILES_PER_B 64  // S / 64

typedef unsigned long long u64;

// ---------------- scratch (device globals; no allocation allowed) ----------------
__device__ unsigned char g_bucket[BB * HH * SS];          // 512 KB
__device__ int           g_st[BB * HH * SS];              // 2 MB  sorted original positions
__device__ float         g_norm[BB * SS];                 // 256 KB
__device__ float         g_logits[BB * HH * SS];          // 2 MB
__device__ float         g_o[(size_t)BB * HH * SS * DD];  // 134 MB

// packed f32x2 FMA (SASS FFMA2). Each 32-bit half is an independent FMA.
__device__ __forceinline__ void ffma2(u64 &acc, u64 a, u64 b) {
    asm volatile("fma.rn.f32x2 %0, %1, %2, %0;" : "+l"(acc) : "l"(a), "l"(b));
}
__device__ __forceinline__ u64 pack2(float a, float b) {
    u64 r;
    asm("mov.b64 %0, {%1, %2};" : "=l"(r) : "f"(a), "f"(b));
    return r;
}
__device__ __forceinline__ float lo2(u64 x) { return __uint_as_float((unsigned)(x & 0xffffffffu)); }
__device__ __forceinline__ float hi2(u64 x) { return __uint_as_float((unsigned)(x >> 32)); }
__device__ __forceinline__ float fsum2(u64 x) { return lo2(x) + hi2(x); }

// =====================================================================
// Probe kernel: keeps ncu's skip-5 capture slot on k_attn.
// =====================================================================
__global__ void k_probe() {}

// =====================================================================
// Kernel 1: hash projection + argmax buckets + token norms
// (unchanged — bit-stable vs reference at rel_err 4.4e-4)
// =====================================================================
__global__ void __launch_bounds__(512) k_hash(const float* __restrict__ qk,
                                              const float* __restrict__ rot) {
    extern __shared__ float sm1[];
    float* qs   = sm1;               // [64][65]
    float* rotF = sm1 + 64 * 65;     // [64][260] f-major

    int tid = threadIdx.x;
    int b   = blockIdx.x >> 6;
    int tb  = (blockIdx.x & 63) * 64;

    for (int i = tid; i < 64 * 64; i += 512) {
        int r = i >> 6, f = i & 63;
        qs[r * 65 + f] = qk[((size_t)(b * SS + tb + r)) * DD + f];
    }
    for (int i = tid; i < 64 * 256; i += 512) {
        int f = i >> 8, c = i & 255;
        rotF[f * 260 + c] = rot[i];
    }
    __syncthreads();

    if (tid < 64) {
        float ssq = 0.f;
        #pragma unroll 8
        for (int f = 0; f < 64; f++) { float x = qs[tid * 65 + f]; ssq += x * x; }
        g_norm[b * SS + tb + tid] = sqrtf(ssq);
    }

    {
        int h   = tid >> 6;          // uniform within each warp
        int tok = tid & 63;

        u64 acc[16];
        #pragma unroll
        for (int i = 0; i < 16; i++) acc[i] = 0ull;

        for (int f = 0; f < 64; f++) {
            float qf = qs[tok * 65 + f];
            u64 qq = pack2(qf, qf);
            const float4* rp = (const float4*)&rotF[f * 260 + h * 32];
            #pragma unroll
            for (int i4 = 0; i4 < 8; i4++) {
                float4 r4 = rp[i4];
                ffma2(acc[2 * i4],     qq, pack2(r4.x, r4.y));
                ffma2(acc[2 * i4 + 1], qq, pack2(r4.z, r4.w));
            }
        }

        float best = lo2(acc[0]); int bi = 0;
        #pragma unroll
        for (int i = 0; i < 16; i++) {
            float vl = lo2(acc[i]), vh = hi2(acc[i]);
            int cl = 2 * i, ch = 2 * i + 1;
            if (cl > 0 && vl > best) { best = vl; bi = cl; }
            if (vh > best)           { best = vh; bi = ch; }
        }
        #pragma unroll
        for (int i = 0; i < 16; i++) {
            float vl = -lo2(acc[i]), vh = -hi2(acc[i]);
            if (vl > best) { best = vl; bi = 32 + 2 * i; }
            if (vh > best) { best = vh; bi = 32 + 2 * i + 1; }
        }
        g_bucket[(size_t)(b * HH + h) * SS + tb + tok] = (unsigned char)bi;
    }
}

// =====================================================================
// Kernel 2: parallel stable counting sort per (b,h) by (bucket, pos).
// 8 warps x 512-token segments. Warp histograms -> segment offsets ->
// match_any rank pass (stable: rounds in token order; lane order within
// a round equals token order; per-warp atomicAdds execute in round order).
// =====================================================================
__global__ void __launch_bounds__(256) k_sort() {
    __shared__ unsigned char bk[SS];
    __shared__ int hist[8][64];
    __shared__ int segoff[8][64];   // absolute start per (warp-seg, bucket)
    __shared__ int tot[64];
    int tid = threadIdx.x;
    int w = tid >> 5, lane = tid & 31;
    int b = blockIdx.x >> 3, h = blockIdx.x & 7;
    size_t base = (size_t)(b * HH + h) * SS;

    for (int i = tid; i < 512; i += 256) ((int*)hist)[i] = 0;
    __syncthreads();

    #pragma unroll 4
    for (int r = 0; r < 16; r++) {
        int t = w * 512 + r * 32 + lane;
        unsigned char bb = g_bucket[base + t];
        bk[t] = bb;
        atomicAdd(&hist[w][bb], 1);
    }
    __syncthreads();

    if (tid < 64) {     // per-bucket: offsets across the 8 segments
        int run = 0;
        #pragma unroll
        for (int w2 = 0; w2 < 8; w2++) { segoff[w2][tid] = run; run += hist[w2][tid]; }
        tot[tid] = run;
    }
    __syncthreads();
    if (tid == 0) {     // exclusive scan of bucket totals
        int run = 0;
        for (int bb = 0; bb < 64; bb++) { int c = tot[bb]; tot[bb] = run; run += c; }
    }
    __syncthreads();
    for (int i = tid; i < 512; i += 256) {
        int w2 = i >> 6, bb = i & 63;
        segoff[w2][bb] += tot[bb];
    }
    __syncthreads();

    for (int r = 0; r < 16; r++) {
        int t = w * 512 + r * 32 + lane;
        int bb = bk[t];
        unsigned mask = __match_any_sync(0xffffffffu, bb);
        int leader = __ffs(mask) - 1;
        int rank = __popc(mask & ((1u << lane) - 1));
        int basepos = 0;
        if (lane == leader) basepos = atomicAdd(&segoff[w][bb], __popc(mask));
        basepos = __shfl_sync(0xffffffffu, basepos, leader);
        g_st[base + basepos + rank] = t;
    }
}

// =====================================================================
// Kernel 3: chunked attention. One block per (b, chunk). 128 threads
// (4 warps x 16-row tiles), 2 CTAs/SM. smem 66560 B:
//   ksf : u64[32 w][132 j] f-major linear (GEMM1), overlaid by
//   attn: float[64][132] after GEMM1 (same 33792 B region)
//   vTf : float[64 d][128 j], 16B XOR swizzle (GEMM2 B operand)
// Per-warp-slice wavefront/FFMA2 ratios: GEMM1 16/64, GEMM2 24/64
// -> fma pipe is the sole binder.
// =====================================================================
__global__ void __launch_bounds__(128, 2) k_attn(const float* __restrict__ qk,
                                                 const float* __restrict__ v) {
    extern __shared__ float sm3[];
    u64*   ksf  = (u64*)sm3;                 // 32*132 u64 = 33792 B
    float* attn = sm3;                       // overlays ksf after GEMM1
    float* vTf  = sm3 + 8448;                // 64*128 floats = 32768 B

    __shared__ int   tkv[128];
    __shared__ float sQ[64];

    int tid = threadIdx.x;
    int b = blockIdx.x >> 9;
    int c = blockIdx.x & 511;
    int cp = (c + CPB - 1) & (CPB - 1);
    int h = c >> 6, hp = cp >> 6;
    size_t baseq = (size_t)(b * HH + h)  * SS + (c  & 63) * 64;
    size_t basep = (size_t)(b * HH + hp) * SS + (cp & 63) * 64;

    if (tid < 64) {
        int t = g_st[baseq + tid];
        tkv[tid] = t;
        sQ[tid] = fmaxf(g_norm[b * SS + t], 1e-12f);
    } else {
        tkv[tid] = g_st[basep + tid - 64];
    }
    __syncthreads();

    // gather K (normalized, f-major) and V (transposed, 16B-swizzled)
    for (int i = tid; i < 128 * 16; i += 128) {
        int j = i >> 4, q4 = i & 15;
        int t = tkv[j];
        size_t rowoff = ((size_t)b * SS + t) * DD + q4 * 4;
        float4 kq = *(const float4*)(qk + rowoff);
        float rn = 1.0f / fmaxf(g_norm[b * SS + t], 1e-12f);
        ksf[(2 * q4)     * 132 + j] = pack2(kq.x * rn, kq.y * rn);
        ksf[(2 * q4 + 1) * 132 + j] = pack2(kq.z * rn, kq.w * rn);

        float4 vv = *(const float4*)(v + rowoff);
        int d0 = q4 * 4, jw = j >> 2, jl = j & 3;
        vTf[((d0 + 0) * 32 + (jw ^ ((d0 + 0) & 31))) * 4 + jl] = vv.x;
        vTf[((d0 + 1) * 32 + (jw ^ ((d0 + 1) & 31))) * 4 + jl] = vv.y;
        vTf[((d0 + 2) * 32 + (jw ^ ((d0 + 2) & 31))) * 4 + jl] = vv.z;
        vTf[((d0 + 3) * 32 + (jw ^ ((d0 + 3) & 31))) * 4 + jl] = vv.w;
    }
    __syncthreads();

    int ty = tid >> 5, tx = tid & 31;
    int r0 = ty * 16;

    // GEMM1: G[i][j] = k_i . k_j  (64 x 128), 16x4 f32x2 tile per thread
    u64 acc[16][4];
    #pragma unroll
    for (int rr = 0; rr < 16; rr++)
        #pragma unroll
        for (int jj = 0; jj < 4; jj++) acc[rr][jj] = 0ull;

    {
        const u64* pc = ksf + tx;                               // per-lane columns
        const ulonglong2* pr2 = (const ulonglong2*)(ksf + r0);  // uniform row pairs
        for (int w = 0; w < 32; w++) {   // f = 2w
            u64 kv2[4];
            #pragma unroll
            for (int jj = 0; jj < 4; jj++)
                kv2[jj] = pc[32 * jj];                   // conflict-free (2 wf each)
            #pragma unroll
            for (int p = 0; p < 8; p++) {
                ulonglong2 rw = pr2[p];                  // uniform 16B (1 wf): rows 2p,2p+1
                #pragma unroll
                for (int jj = 0; jj < 4; jj++) {
                    ffma2(acc[2 * p][jj],     rw.x, kv2[jj]);
                    ffma2(acc[2 * p + 1][jj], rw.y, kv2[jj]);
                }
            }
            pc += 132; pr2 += 66;
        }
    }

    // masks + softmax entirely in registers (16 rows per warp)
    float a[16][4];
    int tkcol[4];
    #pragma unroll
    for (int jj = 0; jj < 4; jj++) tkcol[jj] = tkv[tx + 32 * jj];

    #pragma unroll
    for (int rr = 0; rr < 16; rr++) {
        int row = r0 + rr;
        int tq  = tkv[row];
        float s = sQ[row] * 0.125f;   // norm_i * D^-0.5
        #pragma unroll
        for (int jj = 0; jj < 4; jj++) {
            float val = fsum2(acc[rr][jj]) * s;
            int tk = tkcol[jj];
            if (tq < tk)  val = -3.402823466e38f;   // causal mask
            if (tq == tk) val = -50000.0f;          // self mask
            a[rr][jj] = val;
        }
        float m = fmaxf(fmaxf(a[rr][0], a[rr][1]), fmaxf(a[rr][2], a[rr][3]));
        #pragma unroll
        for (int o = 16; o > 0; o >>= 1) m = fmaxf(m, __shfl_xor_sync(0xffffffffu, m, o));
        float sum = 0.f;
        #pragma unroll
        for (int jj = 0; jj < 4; jj++) { a[rr][jj] = __expf(a[rr][jj] - m); sum += a[rr][jj]; }
        #pragma unroll
        for (int o = 16; o > 0; o >>= 1) sum += __shfl_xor_sync(0xffffffffu, sum, o);
        float inv = 1.0f / sum;
        #pragma unroll
        for (int jj = 0; jj < 4; jj++) a[rr][jj] *= inv;
        if (tx == 0)
            g_logits[(size_t)(b * HH + h) * SS + tq] = m + __logf(sum);
    }
    __syncthreads();   // all warps done reading ksf before overlay writes

    #pragma unroll
    for (int rr = 0; rr < 16; rr++) {
        int row = r0 + rr;
        #pragma unroll
        for (int jj = 0; jj < 4; jj++)
            attn[row * 132 + tx + 32 * jj] = a[rr][jj];
    }
    __syncwarp();      // GEMM2 reads only this warp's own rows

    // GEMM2: out[i][d] = sum_j attn[i][j] * vT[d][j]; 16x2 tile, j-step 4
    {
        u64 acc2[16][2];
        #pragma unroll
        for (int rr = 0; rr < 16; rr++) { acc2[rr][0] = 0ull; acc2[rr][1] = 0ull; }

        const float* arow = attn + r0 * 132;         // warp-uniform base
        for (int jw = 0; jw < 32; jw++) {            // j = 4*jw
            ulonglong2 w0 = *(const ulonglong2*)&vTf[(tx * 32 + (jw ^ tx)) * 4];
            ulonglong2 w1 = *(const ulonglong2*)&vTf[((tx + 32) * 32 + (jw ^ tx)) * 4];
            #pragma unroll
            for (int rr = 0; rr < 16; rr++) {
                ulonglong2 av = *(const ulonglong2*)&arow[rr * 132 + 4 * jw]; // uniform
                ffma2(acc2[rr][0], av.x, w0.x);
                ffma2(acc2[rr][0], av.y, w0.y);
                ffma2(acc2[rr][1], av.x, w1.x);
                ffma2(acc2[rr][1], av.y, w1.y);
            }
        }
        #pragma unroll
        for (int rr = 0; rr < 16; rr++) {
            int row = r0 + rr;
            int t = tkv[row];
            float* dst = &g_o[((size_t)(b * HH + h) * SS + t) * DD];
            dst[tx]      = fsum2(acc2[rr][0]);
            dst[tx + 32] = fsum2(acc2[rr][1]);
        }
    }
}

// =====================================================================
// Kernel 4: combine hash rounds via softmax over per-hash logits
// =====================================================================
__global__ void __launch_bounds__(256) k_combine(float* __restrict__ out) {
    int gid = blockIdx.x * 256 + threadIdx.x;   // B*S*4 total
    int token = gid >> 2, q = gid & 3;
    int b = token >> 12, t = token & 4095;

    float l[HH];
    #pragma unroll
    for (int h = 0; h < HH; h++)
        l[h] = g_logits[(size_t)(b * HH + h) * SS + t];
    float m = l[0];
    #pragma unroll
    for (int h = 1; h < HH; h++) m = fmaxf(m, l[h]);
    float w[HH]; float sum = 0.f;
    #pragma unroll
    for (int h = 0; h < HH; h++) { w[h] = expf(l[h] - m); sum += w[h]; }
    float inv = 1.0f / sum;

    float4 acc[4];
    #pragma unroll
    for (int k = 0; k < 4; k++) acc[k] = make_float4(0.f, 0.f, 0.f, 0.f);
    #pragma unroll
    for (int h = 0; h < HH; h++) {
        const float4* src =
            (const float4*)&g_o[((size_t)(b * HH + h) * SS + t) * DD + q * 16];
        float wh = w[h] * inv;
        #pragma unroll
        for (int k = 0; k < 4; k++) {
            float4 x = src[k];
            acc[k].x += x.x * wh; acc[k].y += x.y * wh;
            acc[k].z += x.z * wh; acc[k].w += x.w * wh;
        }
    }
    float4* dst = (float4*)(out + ((size_t)b * SS + t) * DD + q * 16);
    #pragma unroll
    for (int k = 0; k < 4; k++) dst[k] = acc[k];
}

// =====================================================================
extern "C" void kernel_launch(void* const* d_in, const int* in_sizes, int n_in,
                              void* d_out, int out_size) {
    const float* qk  = (const float*)d_in[0];
    const float* v   = (const float*)d_in[1];
    const float* rot = (const float*)d_in[2];
    float* out = (float*)d_out;

    const int smem1 = (64 * 65 + 64 * 260) * 4;   // 83200 B
    const int smem3 = (8448 + 8192) * 4;          // 66560 B -> 2 CTAs/SM (reg-bound)
    cudaFuncSetAttribute(k_hash, cudaFuncAttributeMaxDynamicSharedMemorySize, smem1);
    cudaFuncSetAttribute(k_attn, cudaFuncAttributeMaxDynamicSharedMemorySize, smem3);

    k_hash<<<BB * TILES_PER_B, 512, smem1>>>(qk, rot);
    k_sort<<<BB * HH, 256>>>();
    k_probe<<<1, 32>>>();   // keeps ncu skip-5 capture on k_attn
    k_attn<<<BB * CPB, 128, smem3>>>(qk, v);
    k_combine<<<BB * SS * 4 / 256, 256>>>(out);
}

// round 11
// speedup vs baseline: 1.0997x; 1.0997x over previous
#include <cuda_runtime.h>
#include <math.h>
#include <float.h>

// LSH attention: B=16, S=4096, D=64, H=8 hashes, bucket_size=64
#define BB 16
#define SS 4096
#define DD 64
#define HH 8
#define NBK 64          // n_buckets
#define CPB 512         // chunks per batch = H * n_buckets
#define TILES_PER_B 64  // S / 64

typedef unsigned long long u64;

// ---------------- scratch (device globals; no allocation allowed) ----------------
__device__ unsigned char g_bucket[BB * HH * SS];          // 512 KB
__device__ int           g_st[BB * HH * SS];              // 2 MB  sorted original positions
__device__ float         g_norm[BB * SS];                 // 256 KB
__device__ float         g_logits[BB * HH * SS];          // 2 MB
__device__ float         g_o[(size_t)BB * HH * SS * DD];  // 134 MB

// packed f32x2 FMA (SASS FFMA2). Each 32-bit half is an independent FMA.
__device__ __forceinline__ void ffma2(u64 &acc, u64 a, u64 b) {
    asm volatile("fma.rn.f32x2 %0, %1, %2, %0;" : "+l"(acc) : "l"(a), "l"(b));
}
__device__ __forceinline__ u64 pack2(float a, float b) {
    u64 r;
    asm("mov.b64 %0, {%1, %2};" : "=l"(r) : "f"(a), "f"(b));
    return r;
}
__device__ __forceinline__ float lo2(u64 x) { return __uint_as_float((unsigned)(x & 0xffffffffu)); }
__device__ __forceinline__ float hi2(u64 x) { return __uint_as_float((unsigned)(x >> 32)); }
__device__ __forceinline__ float fsum2(u64 x) { return lo2(x) + hi2(x); }

// =====================================================================
// Probe kernel: keeps ncu's skip-5 capture slot on k_attn.
// =====================================================================
__global__ void k_probe() {}

// =====================================================================
// Kernel 1: hash projection + argmax buckets + token norms
// rot pre-paired into u64 in smem -> inner loop has zero pack MOVs for
// the B operand. Per-output arithmetic unchanged (each FFMA2 half is a
// single-accumulator ascending-f chain) -> bit-identical buckets.
// =====================================================================
__global__ void __launch_bounds__(512) k_hash(const float* __restrict__ qk,
                                              const float* __restrict__ rot) {
    extern __shared__ float sm1[];
    float* qs    = sm1;                    // [64][65]
    u64*   rotF8 = (u64*)(sm1 + 64 * 66);  // [64 f][130] u64 (cols pre-paired)

    int tid = threadIdx.x;
    int b   = blockIdx.x >> 6;
    int tb  = (blockIdx.x & 63) * 64;

    for (int i = tid; i < 64 * 64; i += 512) {
        int r = i >> 6, f = i & 63;
        qs[r * 65 + f] = qk[((size_t)(b * SS + tb + r)) * DD + f];
    }
    // rot global layout: (1, D, H, 32): row f = 256 contiguous floats
    for (int i = tid; i < 64 * 128; i += 512) {
        int f = i >> 7, c2 = i & 127;
        float2 rv = *(const float2*)&rot[f * 256 + 2 * c2];
        rotF8[f * 130 + c2] = pack2(rv.x, rv.y);
    }
    __syncthreads();

    if (tid < 64) {
        float ssq = 0.f;
        #pragma unroll 8
        for (int f = 0; f < 64; f++) { float x = qs[tid * 65 + f]; ssq += x * x; }
        g_norm[b * SS + tb + tid] = sqrtf(ssq);
    }

    {
        int h   = tid >> 6;          // uniform within each warp
        int tok = tid & 63;

        u64 acc[16];
        #pragma unroll
        for (int i = 0; i < 16; i++) acc[i] = 0ull;

        const ulonglong2* rp = (const ulonglong2*)(rotF8 + h * 16);
        for (int f = 0; f < 64; f++) {
            float qf = qs[tok * 65 + f];
            u64 qq = pack2(qf, qf);
            #pragma unroll
            for (int p = 0; p < 8; p++) {
                ulonglong2 rr = rp[p];           // uniform 16B load
                ffma2(acc[2 * p],     qq, rr.x);
                ffma2(acc[2 * p + 1], qq, rr.y);
            }
            rp += 65;                            // 130 u64 / 2
        }

        float best = lo2(acc[0]); int bi = 0;
        #pragma unroll
        for (int i = 0; i < 16; i++) {
            float vl = lo2(acc[i]), vh = hi2(acc[i]);
            int cl = 2 * i, ch = 2 * i + 1;
            if (cl > 0 && vl > best) { best = vl; bi = cl; }
            if (vh > best)           { best = vh; bi = ch; }
        }
        #pragma unroll
        for (int i = 0; i < 16; i++) {
            float vl = -lo2(acc[i]), vh = -hi2(acc[i]);
            if (vl > best) { best = vl; bi = 32 + 2 * i; }
            if (vh > best) { best = vh; bi = 32 + 2 * i + 1; }
        }
        g_bucket[(size_t)(b * HH + h) * SS + tb + tok] = (unsigned char)bi;
    }
}

// =====================================================================
// Kernel 2: parallel stable counting sort per (b,h) by (bucket, pos).
// =====================================================================
__global__ void __launch_bounds__(256) k_sort() {
    __shared__ unsigned char bk[SS];
    __shared__ int hist[8][64];
    __shared__ int segoff[8][64];
    __shared__ int tot[64];
    int tid = threadIdx.x;
    int w = tid >> 5, lane = tid & 31;
    int b = blockIdx.x >> 3, h = blockIdx.x & 7;
    size_t base = (size_t)(b * HH + h) * SS;

    for (int i = tid; i < 512; i += 256) ((int*)hist)[i] = 0;
    __syncthreads();

    #pragma unroll 4
    for (int r = 0; r < 16; r++) {
        int t = w * 512 + r * 32 + lane;
        unsigned char bb = g_bucket[base + t];
        bk[t] = bb;
        atomicAdd(&hist[w][bb], 1);
    }
    __syncthreads();

    if (tid < 64) {
        int run = 0;
        #pragma unroll
        for (int w2 = 0; w2 < 8; w2++) { segoff[w2][tid] = run; run += hist[w2][tid]; }
        tot[tid] = run;
    }
    __syncthreads();
    if (tid == 0) {
        int run = 0;
        for (int bb = 0; bb < 64; bb++) { int c = tot[bb]; tot[bb] = run; run += c; }
    }
    __syncthreads();
    for (int i = tid; i < 512; i += 256) {
        int w2 = i >> 6, bb = i & 63;
        segoff[w2][bb] += tot[bb];
    }
    __syncthreads();

    for (int r = 0; r < 16; r++) {
        int t = w * 512 + r * 32 + lane;
        int bb = bk[t];
        unsigned mask = __match_any_sync(0xffffffffu, bb);
        int leader = __ffs(mask) - 1;
        int rank = __popc(mask & ((1u << lane) - 1));
        int basepos = 0;
        if (lane == leader) basepos = atomicAdd(&segoff[w][bb], __popc(mask));
        basepos = __shfl_sync(0xffffffffu, basepos, leader);
        g_st[base + basepos + rank] = t;
    }
}

// =====================================================================
// Kernel 3: chunked attention — R8 shape (256 thr, 8x4 tiles, 2 CTA/SM)
// with GEMM1 row operands pair-loaded (stride 132, ulonglong2):
// per-warp-slice LDS 16 -> 12 wf per 32 FFMA2.
//   ksf : u64[32 w][132 j] f-major linear
//   vTf : float[64 d][128 j], 16B XOR swizzle
//   attn: float[64][132]
// =====================================================================
__global__ void __launch_bounds__(256, 2) k_attn(const float* __restrict__ qk,
                                                 const float* __restrict__ v) {
    extern __shared__ float sm3[];
    u64*   ksf  = (u64*)sm3;                 // 32*132 u64 = 33792 B
    float* vTf  = sm3 + 8448;                // 64*128 floats = 32768 B
    float* attn = sm3 + 8448 + 8192;         // 64*132 floats = 33792 B

    __shared__ int   tkv[128];
    __shared__ float sQ[64];

    int tid = threadIdx.x;
    int b = blockIdx.x >> 9;
    int c = blockIdx.x & 511;
    int cp = (c + CPB - 1) & (CPB - 1);
    int h = c >> 6, hp = cp >> 6;
    size_t baseq = (size_t)(b * HH + h)  * SS + (c  & 63) * 64;
    size_t basep = (size_t)(b * HH + hp) * SS + (cp & 63) * 64;

    if (tid < 64) {
        int t = g_st[baseq + tid];
        tkv[tid] = t;
        sQ[tid] = fmaxf(g_norm[b * SS + t], 1e-12f);
    } else if (tid < 128) {
        tkv[tid] = g_st[basep + tid - 64];
    }
    __syncthreads();

    // gather K (normalized, f-major) and V (transposed, 16B-swizzled)
    for (int i = tid; i < 128 * 16; i += 256) {
        int j = i >> 4, q4 = i & 15;
        int t = tkv[j];
        size_t rowoff = ((size_t)b * SS + t) * DD + q4 * 4;
        float4 kq = *(const float4*)(qk + rowoff);
        float rn = 1.0f / fmaxf(g_norm[b * SS + t], 1e-12f);
        ksf[(2 * q4)     * 132 + j] = pack2(kq.x * rn, kq.y * rn);
        ksf[(2 * q4 + 1) * 132 + j] = pack2(kq.z * rn, kq.w * rn);

        float4 vv = *(const float4*)(v + rowoff);
        int d0 = q4 * 4, jw = j >> 2, jl = j & 3;
        vTf[((d0 + 0) * 32 + (jw ^ ((d0 + 0) & 31))) * 4 + jl] = vv.x;
        vTf[((d0 + 1) * 32 + (jw ^ ((d0 + 1) & 31))) * 4 + jl] = vv.y;
        vTf[((d0 + 2) * 32 + (jw ^ ((d0 + 2) & 31))) * 4 + jl] = vv.z;
        vTf[((d0 + 3) * 32 + (jw ^ ((d0 + 3) & 31))) * 4 + jl] = vv.w;
    }
    __syncthreads();

    int ty = tid >> 5, tx = tid & 31;

    // GEMM1: G[i][j] = k_i . k_j  (64 x 128), 8x4 f32x2 tile per thread
    u64 acc[8][4];
    #pragma unroll
    for (int rr = 0; rr < 8; rr++)
        #pragma unroll
        for (int jj = 0; jj < 4; jj++) acc[rr][jj] = 0ull;

    {
        const u64* pc = ksf + tx;                                   // per-lane columns
        const ulonglong2* pr2 = (const ulonglong2*)(ksf + ty * 8);  // uniform row pairs
        for (int w = 0; w < 32; w++) {   // f = 2w
            u64 kv2[4];
            #pragma unroll
            for (int jj = 0; jj < 4; jj++)
                kv2[jj] = pc[32 * jj];               // lane-consecutive, conflict-free
            #pragma unroll
            for (int p = 0; p < 4; p++) {
                ulonglong2 rw = pr2[p];              // uniform 16B: rows 2p, 2p+1
                #pragma unroll
                for (int jj = 0; jj < 4; jj++) {
                    ffma2(acc[2 * p][jj],     rw.x, kv2[jj]);
                    ffma2(acc[2 * p + 1][jj], rw.y, kv2[jj]);
                }
            }
            pc += 132; pr2 += 66;
        }
    }

    // masks + softmax entirely in registers (row fully owned by one warp)
    float a[8][4];
    int tkcol[4];
    #pragma unroll
    for (int jj = 0; jj < 4; jj++) tkcol[jj] = tkv[tx + 32 * jj];

    #pragma unroll
    for (int rr = 0; rr < 8; rr++) {
        int row = ty * 8 + rr;
        int tq  = tkv[row];
        float s = sQ[row] * 0.125f;   // norm_i * D^-0.5
        #pragma unroll
        for (int jj = 0; jj < 4; jj++) {
            float val = fsum2(acc[rr][jj]) * s;
            int tk = tkcol[jj];
            if (tq < tk)  val = -3.402823466e38f;   // causal mask
            if (tq == tk) val = -50000.0f;          // self mask
            a[rr][jj] = val;
        }
        float m = fmaxf(fmaxf(a[rr][0], a[rr][1]), fmaxf(a[rr][2], a[rr][3]));
        #pragma unroll
        for (int o = 16; o > 0; o >>= 1) m = fmaxf(m, __shfl_xor_sync(0xffffffffu, m, o));
        float sum = 0.f;
        #pragma unroll
        for (int jj = 0; jj < 4; jj++) { a[rr][jj] = __expf(a[rr][jj] - m); sum += a[rr][jj]; }
        #pragma unroll
        for (int o = 16; o > 0; o >>= 1) sum += __shfl_xor_sync(0xffffffffu, sum, o);
        float inv = 1.0f / sum;
        #pragma unroll
        for (int jj = 0; jj < 4; jj++) a[rr][jj] *= inv;
        if (tx == 0)
            g_logits[(size_t)(b * HH + h) * SS + tq] = m + __logf(sum);
    }

    #pragma unroll
    for (int rr = 0; rr < 8; rr++) {
        int row = ty * 8 + rr;
        #pragma unroll
        for (int jj = 0; jj < 4; jj++)
            attn[row * 132 + tx + 32 * jj] = a[rr][jj];
    }
    __syncwarp();   // GEMM2 reads only this warp's own attn rows

    // GEMM2: out[i][d] = sum_j attn[i][j] * vT[d][j]; 8x2 tile, j-step 4
    {
        u64 acc2[8][2];
        #pragma unroll
        for (int rr = 0; rr < 8; rr++) { acc2[rr][0] = 0ull; acc2[rr][1] = 0ull; }

        const float* arow = attn + (ty * 8) * 132;   // warp-uniform base
        for (int jw = 0; jw < 32; jw++) {            // j = 4*jw
            ulonglong2 w0 = *(const ulonglong2*)&vTf[(tx * 32 + (jw ^ tx)) * 4];
            ulonglong2 w1 = *(const ulonglong2*)&vTf[((tx + 32) * 32 + (jw ^ tx)) * 4];
            #pragma unroll
            for (int rr = 0; rr < 8; rr++) {
                ulonglong2 av = *(const ulonglong2*)&arow[rr * 132 + 4 * jw]; // uniform
                ffma2(acc2[rr][0], av.x, w0.x);
                ffma2(acc2[rr][0], av.y, w0.y);
                ffma2(acc2[rr][1], av.x, w1.x);
                ffma2(acc2[rr][1], av.y, w1.y);
            }
        }
        #pragma unroll
        for (int rr = 0; rr < 8; rr++) {
            int row = ty * 8 + rr;
            int t = tkv[row];
            float* dst = &g_o[((size_t)(b * HH + h) * SS + t) * DD];
            dst[tx]      = fsum2(acc2[rr][0]);
            dst[tx + 32] = fsum2(acc2[rr][1]);
        }
    }
}

// =====================================================================
// Kernel 4: combine hash rounds via softmax over per-hash logits
// =====================================================================
__global__ void __launch_bounds__(256) k_combine(float* __restrict__ out) {
    int gid = blockIdx.x * 256 + threadIdx.x;   // B*S*4 total
    int token = gid >> 2, q = gid & 3;
    int b = token >> 12, t = token & 4095;

    float l[HH];
    #pragma unroll
    for (int h = 0; h < HH; h++)
        l[h] = g_logits[(size_t)(b * HH + h) * SS + t];
    float m = l[0];
    #pragma unroll
    for (int h = 1; h < HH; h++) m = fmaxf(m, l[h]);
    float w[HH]; float sum = 0.f;
    #pragma unroll
    for (int h = 0; h < HH; h++) { w[h] = expf(l[h] - m); sum += w[h]; }
    float inv = 1.0f / sum;

    float4 acc[4];
    #pragma unroll
    for (int k = 0; k < 4; k++) acc[k] = make_float4(0.f, 0.f, 0.f, 0.f);
    #pragma unroll
    for (int h = 0; h < HH; h++) {
        const float4* src =
            (const float4*)&g_o[((size_t)(b * HH + h) * SS + t) * DD + q * 16];
        float wh = w[h] * inv;
        #pragma unroll
        for (int k = 0; k < 4; k++) {
            float4 x = src[k];
            acc[k].x += x.x * wh; acc[k].y += x.y * wh;
            acc[k].z += x.z * wh; acc[k].w += x.w * wh;
        }
    }
    float4* dst = (float4*)(out + ((size_t)b * SS + t) * DD + q * 16);
    #pragma unroll
    for (int k = 0; k < 4; k++) dst[k] = acc[k];
}

// =====================================================================
extern "C" void kernel_launch(void* const* d_in, const int* in_sizes, int n_in,
                              void* d_out, int out_size) {
    const float* qk  = (const float*)d_in[0];
    const float* v   = (const float*)d_in[1];
    const float* rot = (const float*)d_in[2];
    float* out = (float*)d_out;

    const int smem1 = 64 * 66 * 4 + 64 * 130 * 8;      // 83456 B
    const int smem3 = (8448 + 8192 + 64 * 132) * 4;    // 100096 B -> 2 CTAs/SM
    cudaFuncSetAttribute(k_hash, cudaFuncAttributeMaxDynamicSharedMemorySize, smem1);
    cudaFuncSetAttribute(k_attn, cudaFuncAttributeMaxDynamicSharedMemorySize, smem3);

    k_hash<<<BB * TILES_PER_B, 512, smem1>>>(qk, rot);
    k_sort<<<BB * HH, 256>>>();
    k_probe<<<1, 32>>>();   // keeps ncu skip-5 capture on k_attn
    k_attn<<<BB * CPB, 256, smem3>>>(qk, v);
    k_combine<<<BB * SS * 4 / 256, 256>>>(out);
}

// round 14
// speedup vs baseline: 1.6403x; 1.4916x over previous
#include <cuda_runtime.h>
#include <cuda_bf16.h>
#include <math.h>
#include <float.h>
#include <stdint.h>

// LSH attention: B=16, S=4096, D=64, H=8 hashes, bucket_size=64
#define BB 16
#define SS 4096
#define DD 64
#define HH 8
#define CPB 512         // chunks per batch = H * n_buckets
#define TILES_PER_B 64  // S / 64

typedef unsigned long long u64;

// ---------------- scratch (device globals; no allocation allowed) ----------------
__device__ unsigned char g_bucket[BB * HH * SS];          // 512 KB
__device__ int           g_st[BB * HH * SS];              // 2 MB
__device__ float         g_norm[BB * SS];                 // 256 KB
__device__ float         g_logits[BB * HH * SS];          // 2 MB
__device__ float         g_o[(size_t)BB * HH * SS * DD];  // 134 MB

// packed f32x2 FMA (SASS FFMA2)
__device__ __forceinline__ void ffma2(u64 &acc, u64 a, u64 b) {
    asm volatile("fma.rn.f32x2 %0, %1, %2, %0;" : "+l"(acc) : "l"(a), "l"(b));
}
__device__ __forceinline__ u64 pack2(float a, float b) {
    u64 r;
    asm("mov.b64 %0, {%1, %2};" : "=l"(r) : "f"(a), "f"(b));
    return r;
}
__device__ __forceinline__ float lo2(u64 x) { return __uint_as_float((unsigned)(x & 0xffffffffu)); }
__device__ __forceinline__ float hi2(u64 x) { return __uint_as_float((unsigned)(x >> 32)); }

// warp-level bf16 tensor-core mma (baseline PTX, sm_80+; legal on sm_103)
__device__ __forceinline__ void mma16816(float* c, const uint32_t* a,
                                         uint32_t b0, uint32_t b1) {
    asm volatile(
        "mma.sync.aligned.m16n8k16.row.col.f32.bf16.bf16.f32 "
        "{%0,%1,%2,%3}, {%4,%5,%6,%7}, {%8,%9}, {%0,%1,%2,%3};"
        : "+f"(c[0]), "+f"(c[1]), "+f"(c[2]), "+f"(c[3])
        : "r"(a[0]), "r"(a[1]), "r"(a[2]), "r"(a[3]), "r"(b0), "r"(b1));
}

// =====================================================================
// Probe kernel: keeps ncu's skip-5 capture slot on k_attn.
// =====================================================================
__global__ void k_probe() {}

// =====================================================================
// Kernel 1: hash projection + argmax buckets + token norms (unchanged)
// =====================================================================
__global__ void __launch_bounds__(512) k_hash(const float* __restrict__ qk,
                                              const float* __restrict__ rot) {
    extern __shared__ float sm1[];
    float* qs    = sm1;                    // [64][65]
    u64*   rotF8 = (u64*)(sm1 + 64 * 66);  // [64 f][130] u64

    int tid = threadIdx.x;
    int b   = blockIdx.x >> 6;
    int tb  = (blockIdx.x & 63) * 64;

    for (int i = tid; i < 64 * 64; i += 512) {
        int r = i >> 6, f = i & 63;
        qs[r * 65 + f] = qk[((size_t)(b * SS + tb + r)) * DD + f];
    }
    for (int i = tid; i < 64 * 128; i += 512) {
        int f = i >> 7, c2 = i & 127;
        float2 rv = *(const float2*)&rot[f * 256 + 2 * c2];
        rotF8[f * 130 + c2] = pack2(rv.x, rv.y);
    }
    __syncthreads();

    if (tid < 64) {
        float ssq = 0.f;
        #pragma unroll 8
        for (int f = 0; f < 64; f++) { float x = qs[tid * 65 + f]; ssq += x * x; }
        g_norm[b * SS + tb + tid] = sqrtf(ssq);
    }

    {
        int h   = tid >> 6;
        int tok = tid & 63;

        u64 acc[16];
        #pragma unroll
        for (int i = 0; i < 16; i++) acc[i] = 0ull;

        const ulonglong2* rp = (const ulonglong2*)(rotF8 + h * 16);
        for (int f = 0; f < 64; f++) {
            float qf = qs[tok * 65 + f];
            u64 qq = pack2(qf, qf);
            #pragma unroll
            for (int p = 0; p < 8; p++) {
                ulonglong2 rr = rp[p];
                ffma2(acc[2 * p],     qq, rr.x);
                ffma2(acc[2 * p + 1], qq, rr.y);
            }
            rp += 65;
        }

        float best = lo2(acc[0]); int bi = 0;
        #pragma unroll
        for (int i = 0; i < 16; i++) {
            float vl = lo2(acc[i]), vh = hi2(acc[i]);
            int cl = 2 * i, ch = 2 * i + 1;
            if (cl > 0 && vl > best) { best = vl; bi = cl; }
            if (vh > best)           { best = vh; bi = ch; }
        }
        #pragma unroll
        for (int i = 0; i < 16; i++) {
            float vl = -lo2(acc[i]), vh = -hi2(acc[i]);
            if (vl > best) { best = vl; bi = 32 + 2 * i; }
            if (vh > best) { best = vh; bi = 32 + 2 * i + 1; }
        }
        g_bucket[(size_t)(b * HH + h) * SS + tb + tok] = (unsigned char)bi;
    }
}

// =====================================================================
// Kernel 2: parallel stable counting sort per (b,h) (unchanged)
// =====================================================================
__global__ void __launch_bounds__(256) k_sort() {
    __shared__ unsigned char bk[SS];
    __shared__ int hist[8][64];
    __shared__ int segoff[8][64];
    __shared__ int tot[64];
    int tid = threadIdx.x;
    int w = tid >> 5, lane = tid & 31;
    int b = blockIdx.x >> 3, h = blockIdx.x & 7;
    size_t base = (size_t)(b * HH + h) * SS;

    for (int i = tid; i < 512; i += 256) ((int*)hist)[i] = 0;
    __syncthreads();

    #pragma unroll 4
    for (int r = 0; r < 16; r++) {
        int t = w * 512 + r * 32 + lane;
        unsigned char bb = g_bucket[base + t];
        bk[t] = bb;
        atomicAdd(&hist[w][bb], 1);
    }
    __syncthreads();

    if (tid < 64) {
        int run = 0;
        #pragma unroll
        for (int w2 = 0; w2 < 8; w2++) { segoff[w2][tid] = run; run += hist[w2][tid]; }
        tot[tid] = run;
    }
    __syncthreads();
    if (tid == 0) {
        int run = 0;
        for (int bb = 0; bb < 64; bb++) { int c = tot[bb]; tot[bb] = run; run += c; }
    }
    __syncthreads();
    for (int i = tid; i < 512; i += 256) {
        int w2 = i >> 6, bb = i & 63;
        segoff[w2][bb] += tot[bb];
    }
    __syncthreads();

    for (int r = 0; r < 16; r++) {
        int t = w * 512 + r * 32 + lane;
        int bb = bk[t];
        unsigned mask = __match_any_sync(0xffffffffu, bb);
        int leader = __ffs(mask) - 1;
        int rank = __popc(mask & ((1u << lane) - 1));
        int basepos = 0;
        if (lane == leader) basepos = atomicAdd(&segoff[w][bb], __popc(mask));
        basepos = __shfl_sync(0xffffffffu, basepos, leader);
        g_st[base + basepos + rank] = t;
    }
}

// =====================================================================
// Kernel 3: chunked attention on mma.sync bf16 tensor cores.
// One block per (b, chunk). 128 threads (4 warps x 16 rows), 3 CTAs/SM.
//
// GEMM1: D1[64][128] = ks_hat · ks_hat^T, 3-pass bf16 split (hi/lo).
// GEMM2: D2[64][64]  = attn · V,          3-pass bf16 split.
// SMEM (72448 B):
//   Khi/Klo : bf16 [128 rows][64 k], stride 36 words (bank-perfect)
//   Aphi/lo : bf16 [64 rows][128 j], stride 68 words  -- overlays Khi/Klo
//   Vphi/lo : bf16 [64 d][128 j],    stride 68 words
// Fragment loads are single LDS.32 (bf16x2 pairs == mma layout).
// Softmax in registers from mma C-fragments (quad shuffles).
// =====================================================================
#define KHI_OFF   0
#define KLO_OFF   18432
#define APHI_OFF  0        // overlays Khi (dead after GEMM1)
#define APLO_OFF  17408
#define VPHI_OFF  36864
#define VPLO_OFF  54272
#define TKV_OFF   71680
#define SQ_OFF    72192
#define SMEM3_SZ  72448

__global__ void __launch_bounds__(128, 3) k_attn(const float* __restrict__ qk,
                                                 const float* __restrict__ v) {
    extern __shared__ char smem[];
    uint32_t* Khi  = (uint32_t*)(smem + KHI_OFF);
    uint32_t* Klo  = (uint32_t*)(smem + KLO_OFF);
    uint32_t* Aphi = (uint32_t*)(smem + APHI_OFF);
    uint32_t* Aplo = (uint32_t*)(smem + APLO_OFF);
    uint32_t* Vphi = (uint32_t*)(smem + VPHI_OFF);
    uint32_t* Vplo = (uint32_t*)(smem + VPLO_OFF);
    int*   tkv = (int*)(smem + TKV_OFF);
    float* sQ  = (float*)(smem + SQ_OFF);

    int tid = threadIdx.x;
    int b = blockIdx.x >> 9;
    int c = blockIdx.x & 511;
    int cp = (c + CPB - 1) & (CPB - 1);
    int h = c >> 6, hp = cp >> 6;
    size_t baseq = (size_t)(b * HH + h)  * SS + (c  & 63) * 64;
    size_t basep = (size_t)(b * HH + hp) * SS + (cp & 63) * 64;

    if (tid < 64) {
        int t = g_st[baseq + tid];
        tkv[tid] = t;
        sQ[tid] = fmaxf(g_norm[b * SS + t], 1e-12f);
    } else {
        tkv[tid] = g_st[basep + tid - 64];
    }
    __syncthreads();

    // ---- gather K (normalized, bf16 hi/lo) and V (transposed, bf16 hi/lo) ----
    for (int i = tid; i < 2048; i += 128) {
        int j = i >> 4, q4 = i & 15;
        int t = tkv[j];
        size_t rowoff = ((size_t)b * SS + t) * DD + q4 * 4;
        float4 kq = *(const float4*)(qk + rowoff);
        float rn = 1.0f / fmaxf(g_norm[b * SS + t], 1e-12f);
        float x0 = kq.x * rn, x1 = kq.y * rn, x2 = kq.z * rn, x3 = kq.w * rn;
        __nv_bfloat16 h0 = __float2bfloat16(x0), h1 = __float2bfloat16(x1);
        __nv_bfloat16 h2 = __float2bfloat16(x2), h3 = __float2bfloat16(x3);
        __nv_bfloat16 l0 = __float2bfloat16(x0 - __bfloat162float(h0));
        __nv_bfloat16 l1 = __float2bfloat16(x1 - __bfloat162float(h1));
        __nv_bfloat16 l2 = __float2bfloat16(x2 - __bfloat162float(h2));
        __nv_bfloat16 l3 = __float2bfloat16(x3 - __bfloat162float(h3));
        int kw = j * 36 + 2 * q4;
        *(__nv_bfloat162*)&Khi[kw]     = __halves2bfloat162(h0, h1);
        *(__nv_bfloat162*)&Khi[kw + 1] = __halves2bfloat162(h2, h3);
        *(__nv_bfloat162*)&Klo[kw]     = __halves2bfloat162(l0, l1);
        *(__nv_bfloat162*)&Klo[kw + 1] = __halves2bfloat162(l2, l3);

        float4 vv = *(const float4*)(v + rowoff);
        float vt[4] = {vv.x, vv.y, vv.z, vv.w};
        #pragma unroll
        for (int dd = 0; dd < 4; dd++) {
            int d = q4 * 4 + dd;
            __nv_bfloat16 vh = __float2bfloat16(vt[dd]);
            __nv_bfloat16 vl = __float2bfloat16(vt[dd] - __bfloat162float(vh));
            int hw = (d * 68 + (j >> 1)) * 2 + (j & 1);
            ((__nv_bfloat16*)Vphi)[hw] = vh;
            ((__nv_bfloat16*)Vplo)[hw] = vl;
        }
    }
    __syncthreads();

    int lane = tid & 31, warp = tid >> 5;
    int q = lane & 3, l4 = lane >> 2;
    int r0 = warp * 16;
    int R0 = r0 + l4;            // thread's first row; second is R0+8

    // ---- GEMM1: 3-pass bf16 split ----
    float c1[16][4];
    #pragma unroll
    for (int n = 0; n < 16; n++)
        #pragma unroll
        for (int e = 0; e < 4; e++) c1[n][e] = 0.f;

    #pragma unroll
    for (int pass = 0; pass < 3; pass++) {
        const uint32_t* Aa = (pass == 2) ? Klo : Khi;
        const uint32_t* Ba = (pass == 1) ? Klo : Khi;
        uint32_t af[4][4];
        #pragma unroll
        for (int k = 0; k < 4; k++) {
            const uint32_t* pa = Aa + R0 * 36 + 8 * k + q;
            af[k][0] = pa[0];
            af[k][1] = pa[8 * 36];
            af[k][2] = pa[4];
            af[k][3] = pa[8 * 36 + 4];
        }
        #pragma unroll
        for (int n = 0; n < 16; n++) {
            const uint32_t* pb = Ba + (n * 8 + l4) * 36 + q;
            #pragma unroll
            for (int k = 0; k < 4; k++)
                mma16816(c1[n], af[k], pb[8 * k], pb[8 * k + 4]);
        }
    }

    // ---- masks + softmax (quad-distributed rows) ----
    int tq0 = tkv[R0], tq1 = tkv[R0 + 8];
    float s0 = sQ[R0] * 0.125f, s1 = sQ[R0 + 8] * 0.125f;
    float sum0 = 0.f, sum1 = 0.f;
    #pragma unroll
    for (int n = 0; n < 16; n++) {
        int j0 = 8 * n + 2 * q;
        int tk0 = tkv[j0], tk1 = tkv[j0 + 1];
        float e;
        e = (tq0 <= tk0) ? 0.f : __expf(s0 * (c1[n][0] - 1.f)); c1[n][0] = e; sum0 += e;
        e = (tq0 <= tk1) ? 0.f : __expf(s0 * (c1[n][1] - 1.f)); c1[n][1] = e; sum0 += e;
        e = (tq1 <= tk0) ? 0.f : __expf(s1 * (c1[n][2] - 1.f)); c1[n][2] = e; sum1 += e;
        e = (tq1 <= tk1) ? 0.f : __expf(s1 * (c1[n][3] - 1.f)); c1[n][3] = e; sum1 += e;
    }
    sum0 += __shfl_xor_sync(0xffffffffu, sum0, 1);
    sum0 += __shfl_xor_sync(0xffffffffu, sum0, 2);
    sum1 += __shfl_xor_sync(0xffffffffu, sum1, 1);
    sum1 += __shfl_xor_sync(0xffffffffu, sum1, 2);

    float inv0, inv1, lse0, lse1;
    if (sum0 == 0.f) {
        int nn = R0 >> 3, qq = (R0 >> 1) & 3, ee = R0 & 1;   // self col j == R0
        if (q == qq) c1[nn][ee] = 1.f;
        inv0 = 1.f; lse0 = -50000.f;
    } else { inv0 = 1.f / sum0; lse0 = s0 + __logf(sum0); }
    if (sum1 == 0.f) {
        int Rs = R0 + 8;
        int nn = Rs >> 3, qq = (Rs >> 1) & 3, ee = Rs & 1;
        if (q == qq) c1[nn][2 + ee] = 1.f;
        inv1 = 1.f; lse1 = -50000.f;
    } else { inv1 = 1.f / sum1; lse1 = s1 + __logf(sum1); }

    if (q == 0) {
        g_logits[(size_t)(b * HH + h) * SS + tq0] = lse0;
        g_logits[(size_t)(b * HH + h) * SS + tq1] = lse1;
    }
    __syncthreads();   // all warps done reading Khi/Klo before overlay writes

    // ---- store attn probs (unnormalized) as bf16 hi/lo pairs ----
    #pragma unroll
    for (int n = 0; n < 16; n++) {
        __nv_bfloat16 h00 = __float2bfloat16(c1[n][0]);
        __nv_bfloat16 h01 = __float2bfloat16(c1[n][1]);
        __nv_bfloat16 h10 = __float2bfloat16(c1[n][2]);
        __nv_bfloat16 h11 = __float2bfloat16(c1[n][3]);
        __nv_bfloat16 g00 = __float2bfloat16(c1[n][0] - __bfloat162float(h00));
        __nv_bfloat16 g01 = __float2bfloat16(c1[n][1] - __bfloat162float(h01));
        __nv_bfloat16 g10 = __float2bfloat16(c1[n][2] - __bfloat162float(h10));
        __nv_bfloat16 g11 = __float2bfloat16(c1[n][3] - __bfloat162float(h11));
        int w0 = R0 * 68 + 4 * n + q;
        int w1 = (R0 + 8) * 68 + 4 * n + q;
        *(__nv_bfloat162*)&Aphi[w0] = __halves2bfloat162(h00, h01);
        *(__nv_bfloat162*)&Aplo[w0] = __halves2bfloat162(g00, g01);
        *(__nv_bfloat162*)&Aphi[w1] = __halves2bfloat162(h10, h11);
        *(__nv_bfloat162*)&Aplo[w1] = __halves2bfloat162(g10, g11);
    }
    __syncwarp();   // GEMM2 A-side reads only this warp's own rows

    // ---- GEMM2: 3-pass (Ahi*Vhi, Ahi*Vlo, Alo*Vhi) ----
    float c2[8][4];
    #pragma unroll
    for (int n = 0; n < 8; n++)
        #pragma unroll
        for (int e = 0; e < 4; e++) c2[n][e] = 0.f;

    {
        uint32_t af2[8][4];
        #pragma unroll
        for (int k = 0; k < 8; k++) {
            const uint32_t* pa = Aphi + R0 * 68 + 8 * k + q;
            af2[k][0] = pa[0];
            af2[k][1] = pa[8 * 68];
            af2[k][2] = pa[4];
            af2[k][3] = pa[8 * 68 + 4];
        }
        #pragma unroll
        for (int pass = 0; pass < 2; pass++) {
            const uint32_t* Ba = pass ? Vplo : Vphi;
            #pragma unroll
            for (int n = 0; n < 8; n++) {
                const uint32_t* pb = Ba + (n * 8 + l4) * 68 + q;
                #pragma unroll
                for (int k = 0; k < 8; k++)
                    mma16816(c2[n], af2[k], pb[8 * k], pb[8 * k + 4]);
            }
        }
        #pragma unroll
        for (int k = 0; k < 8; k++) {
            const uint32_t* pa = Aplo + R0 * 68 + 8 * k + q;
            af2[k][0] = pa[0];
            af2[k][1] = pa[8 * 68];
            af2[k][2] = pa[4];
            af2[k][3] = pa[8 * 68 + 4];
        }
        #pragma unroll
        for (int n = 0; n < 8; n++) {
            const uint32_t* pb = Vphi + (n * 8 + l4) * 68 + q;
            #pragma unroll
            for (int k = 0; k < 8; k++)
                mma16816(c2[n], af2[k], pb[8 * k], pb[8 * k + 4]);
        }
    }

    // ---- normalize + scatter ----
    float* dst0 = &g_o[((size_t)(b * HH + h) * SS + tq0) * DD];
    float* dst1 = &g_o[((size_t)(b * HH + h) * SS + tq1) * DD];
    #pragma unroll
    for (int n = 0; n < 8; n++) {
        int col = 8 * n + 2 * q;
        *(float2*)(dst0 + col) = make_float2(c2[n][0] * inv0, c2[n][1] * inv0);
        *(float2*)(dst1 + col) = make_float2(c2[n][2] * inv1, c2[n][3] * inv1);
    }
}

// =====================================================================
// Kernel 4: combine hash rounds via softmax over per-hash logits
// =====================================================================
__global__ void __launch_bounds__(256) k_combine(float* __restrict__ out) {
    int gid = blockIdx.x * 256 + threadIdx.x;
    int token = gid >> 2, q = gid & 3;
    int b = token >> 12, t = token & 4095;

    float l[HH];
    #pragma unroll
    for (int h = 0; h < HH; h++)
        l[h] = g_logits[(size_t)(b * HH + h) * SS + t];
    float m = l[0];
    #pragma unroll
    for (int h = 1; h < HH; h++) m = fmaxf(m, l[h]);
    float w[HH]; float sum = 0.f;
    #pragma unroll
    for (int h = 0; h < HH; h++) { w[h] = expf(l[h] - m); sum += w[h]; }
    float inv = 1.0f / sum;

    float4 acc[4];
    #pragma unroll
    for (int k = 0; k < 4; k++) acc[k] = make_float4(0.f, 0.f, 0.f, 0.f);
    #pragma unroll
    for (int h = 0; h < HH; h++) {
        const float4* src =
            (const float4*)&g_o[((size_t)(b * HH + h) * SS + t) * DD + q * 16];
        float wh = w[h] * inv;
        #pragma unroll
        for (int k = 0; k < 4; k++) {
            float4 x = src[k];
            acc[k].x += x.x * wh; acc[k].y += x.y * wh;
            acc[k].z += x.z * wh; acc[k].w += x.w * wh;
        }
    }
    float4* dst = (float4*)(out + ((size_t)b * SS + t) * DD + q * 16);
    #pragma unroll
    for (int k = 0; k < 4; k++) dst[k] = acc[k];
}

// =====================================================================
extern "C" void kernel_launch(void* const* d_in, const int* in_sizes, int n_in,
                              void* d_out, int out_size) {
    const float* qk  = (const float*)d_in[0];
    const float* v   = (const float*)d_in[1];
    const float* rot = (const float*)d_in[2];
    float* out = (float*)d_out;

    const int smem1 = 64 * 66 * 4 + 64 * 130 * 8;   // 83456 B
    const int smem3 = SMEM3_SZ;                     // 72448 B -> 3 CTAs/SM
    cudaFuncSetAttribute(k_hash, cudaFuncAttributeMaxDynamicSharedMemorySize, smem1);
    cudaFuncSetAttribute(k_attn, cudaFuncAttributeMaxDynamicSharedMemorySize, smem3);

    k_hash<<<BB * TILES_PER_B, 512, smem1>>>(qk, rot);
    k_sort<<<BB * HH, 256>>>();
    k_probe<<<1, 32>>>();   // keeps ncu skip-5 capture on k_attn
    k_attn<<<BB * CPB, 128, smem3>>>(qk, v);
    k_combine<<<BB * SS * 4 / 256, 256>>>(out);
}

// round 15
// speedup vs baseline: 2.2280x; 1.3583x over previous
#include <cuda_runtime.h>
#include <cuda_fp16.h>
#include <math.h>
#include <float.h>
#include <stdint.h>

// LSH attention: B=16, S=4096, D=64, H=8 hashes, bucket_size=64
#define BB 16
#define SS 4096
#define DD 64
#define HH 8
#define CPB 512
#define TILES_PER_B 64

typedef unsigned long long u64;

// ---------------- scratch (device globals) ----------------
__device__ unsigned char g_bucket[BB * HH * SS];
__device__ int           g_st[BB * HH * SS];
__device__ float         g_norm[BB * SS];
__device__ float         g_logits[BB * HH * SS];
__device__ float         g_o[(size_t)BB * HH * SS * DD];

__device__ __forceinline__ void ffma2(u64 &acc, u64 a, u64 b) {
    asm volatile("fma.rn.f32x2 %0, %1, %2, %0;" : "+l"(acc) : "l"(a), "l"(b));
}
__device__ __forceinline__ u64 pack2(float a, float b) {
    u64 r;
    asm("mov.b64 %0, {%1, %2};" : "=l"(r) : "f"(a), "f"(b));
    return r;
}
__device__ __forceinline__ float lo2(u64 x) { return __uint_as_float((unsigned)(x & 0xffffffffu)); }
__device__ __forceinline__ float hi2(u64 x) { return __uint_as_float((unsigned)(x >> 32)); }

__device__ __forceinline__ uint32_t smem_u32(const void* p) {
    uint32_t a;
    asm("{ .reg .u64 t; cvta.to.shared.u64 t, %1; cvt.u32.u64 %0, t; }" : "=r"(a) : "l"(p));
    return a;
}
// fp16 tensor-core mma (baseline PTX sm_80+, legal on sm_103)
__device__ __forceinline__ void mma16816(float* c, const uint32_t* a,
                                         uint32_t b0, uint32_t b1) {
    asm volatile(
        "mma.sync.aligned.m16n8k16.row.col.f32.f16.f16.f32 "
        "{%0,%1,%2,%3}, {%4,%5,%6,%7}, {%8,%9}, {%0,%1,%2,%3};"
        : "+f"(c[0]), "+f"(c[1]), "+f"(c[2]), "+f"(c[3])
        : "r"(a[0]), "r"(a[1]), "r"(a[2]), "r"(a[3]), "r"(b0), "r"(b1));
}
__device__ __forceinline__ void ldsm_x4(uint32_t* r, uint32_t addr) {
    asm volatile("ldmatrix.sync.aligned.m8n8.x4.shared.b16 {%0,%1,%2,%3}, [%4];"
                 : "=r"(r[0]), "=r"(r[1]), "=r"(r[2]), "=r"(r[3]) : "r"(addr));
}

// =====================================================================
__global__ void k_probe() {}

// =====================================================================
// Kernel 1: hash projection + argmax buckets + token norms (unchanged)
// =====================================================================
__global__ void __launch_bounds__(512) k_hash(const float* __restrict__ qk,
                                              const float* __restrict__ rot) {
    extern __shared__ float sm1[];
    float* qs    = sm1;                    // [64][65]
    u64*   rotF8 = (u64*)(sm1 + 64 * 66);  // [64 f][130] u64

    int tid = threadIdx.x;
    int b   = blockIdx.x >> 6;
    int tb  = (blockIdx.x & 63) * 64;

    for (int i = tid; i < 64 * 64; i += 512) {
        int r = i >> 6, f = i & 63;
        qs[r * 65 + f] = qk[((size_t)(b * SS + tb + r)) * DD + f];
    }
    for (int i = tid; i < 64 * 128; i += 512) {
        int f = i >> 7, c2 = i & 127;
        float2 rv = *(const float2*)&rot[f * 256 + 2 * c2];
        rotF8[f * 130 + c2] = pack2(rv.x, rv.y);
    }
    __syncthreads();

    if (tid < 64) {
        float ssq = 0.f;
        #pragma unroll 8
        for (int f = 0; f < 64; f++) { float x = qs[tid * 65 + f]; ssq += x * x; }
        g_norm[b * SS + tb + tid] = sqrtf(ssq);
    }

    {
        int h   = tid >> 6;
        int tok = tid & 63;

        u64 acc[16];
        #pragma unroll
        for (int i = 0; i < 16; i++) acc[i] = 0ull;

        const ulonglong2* rp = (const ulonglong2*)(rotF8 + h * 16);
        for (int f = 0; f < 64; f++) {
            float qf = qs[tok * 65 + f];
            u64 qq = pack2(qf, qf);
            #pragma unroll
            for (int p = 0; p < 8; p++) {
                ulonglong2 rr = rp[p];
                ffma2(acc[2 * p],     qq, rr.x);
                ffma2(acc[2 * p + 1], qq, rr.y);
            }
            rp += 65;
        }

        float best = lo2(acc[0]); int bi = 0;
        #pragma unroll
        for (int i = 0; i < 16; i++) {
            float vl = lo2(acc[i]), vh = hi2(acc[i]);
            int cl = 2 * i, ch = 2 * i + 1;
            if (cl > 0 && vl > best) { best = vl; bi = cl; }
            if (vh > best)           { best = vh; bi = ch; }
        }
        #pragma unroll
        for (int i = 0; i < 16; i++) {
            float vl = -lo2(acc[i]), vh = -hi2(acc[i]);
            if (vl > best) { best = vl; bi = 32 + 2 * i; }
            if (vh > best) { best = vh; bi = 32 + 2 * i + 1; }
        }
        g_bucket[(size_t)(b * HH + h) * SS + tb + tok] = (unsigned char)bi;
    }
}

// =====================================================================
// Kernel 2: parallel stable counting sort per (b,h) (unchanged)
// =====================================================================
__global__ void __launch_bounds__(256) k_sort() {
    __shared__ unsigned char bk[SS];
    __shared__ int hist[8][64];
    __shared__ int segoff[8][64];
    __shared__ int tot[64];
    int tid = threadIdx.x;
    int w = tid >> 5, lane = tid & 31;
    int b = blockIdx.x >> 3, h = blockIdx.x & 7;
    size_t base = (size_t)(b * HH + h) * SS;

    for (int i = tid; i < 512; i += 256) ((int*)hist)[i] = 0;
    __syncthreads();

    #pragma unroll 4
    for (int r = 0; r < 16; r++) {
        int t = w * 512 + r * 32 + lane;
        unsigned char bb = g_bucket[base + t];
        bk[t] = bb;
        atomicAdd(&hist[w][bb], 1);
    }
    __syncthreads();

    if (tid < 64) {
        int run = 0;
        #pragma unroll
        for (int w2 = 0; w2 < 8; w2++) { segoff[w2][tid] = run; run += hist[w2][tid]; }
        tot[tid] = run;
    }
    __syncthreads();
    if (tid == 0) {
        int run = 0;
        for (int bb = 0; bb < 64; bb++) { int c = tot[bb]; tot[bb] = run; run += c; }
    }
    __syncthreads();
    for (int i = tid; i < 512; i += 256) {
        int w2 = i >> 6, bb = i & 63;
        segoff[w2][bb] += tot[bb];
    }
    __syncthreads();

    for (int r = 0; r < 16; r++) {
        int t = w * 512 + r * 32 + lane;
        int bb = bk[t];
        unsigned mask = __match_any_sync(0xffffffffu, bb);
        int leader = __ffs(mask) - 1;
        int rank = __popc(mask & ((1u << lane) - 1));
        int basepos = 0;
        if (lane == leader) basepos = atomicAdd(&segoff[w][bb], __popc(mask));
        basepos = __shfl_sync(0xffffffffu, basepos, leader);
        g_st[base + basepos + rank] = t;
    }
}

// =====================================================================
// Kernel 3: chunked attention, single-pass fp16 mma + ldmatrix.
// 128 threads (4 warps x 16 rows), 4 CTAs/SM (smem 54 KB, <=128 regs).
// SMEM:
//   Kh  : fp16 [128 rows][72 halves stride] (144 B/row)  @0      18432 B
//   Vh  : fp16 [64 d][136 halves stride]    (272 B/row)  @18432  17408 B
//   At  : fp16 [64 rows][136 halves stride]              @35840  17408 B
//   tkv @53248 (512B), sQ @53760 (256B)                   total   54016 B
// All LDSM row-fetches conflict-free (strides 144/272 = 4 banks/row step).
// =====================================================================
#define KH_OFF   0
#define VH_OFF   18432
#define AT_OFF   35840
#define TKV_OFF  53248
#define SQ_OFF   53760
#define SMEM3_SZ 54016

__global__ void __launch_bounds__(128, 4) k_attn(const float* __restrict__ qk,
                                                 const float* __restrict__ v) {
    extern __shared__ char smem[];
    const uint32_t sb = smem_u32(smem);
    int*   tkv = (int*)(smem + TKV_OFF);
    float* sQ  = (float*)(smem + SQ_OFF);

    int tid = threadIdx.x;
    int b = blockIdx.x >> 9;
    int c = blockIdx.x & 511;
    int cp = (c + CPB - 1) & (CPB - 1);
    int h = c >> 6, hp = cp >> 6;
    size_t baseq = (size_t)(b * HH + h)  * SS + (c  & 63) * 64;
    size_t basep = (size_t)(b * HH + hp) * SS + (cp & 63) * 64;

    if (tid < 64) {
        int t = g_st[baseq + tid];
        tkv[tid] = t;
        sQ[tid] = fmaxf(g_norm[b * SS + t], 1e-12f);
    } else {
        tkv[tid] = g_st[basep + tid - 64];
    }
    __syncthreads();

    // ---- gather K (normalized fp16) and V (transposed fp16) ----
    __half* KhH = (__half*)(smem + KH_OFF);
    __half* VhH = (__half*)(smem + VH_OFF);
    for (int i = tid; i < 2048; i += 128) {
        int j = i >> 4, q4 = i & 15;
        int t = tkv[j];
        size_t rowoff = ((size_t)b * SS + t) * DD + q4 * 4;
        float4 kq = *(const float4*)(qk + rowoff);
        float rn = 1.0f / fmaxf(g_norm[b * SS + t], 1e-12f);
        __half2* kd = (__half2*)(KhH + j * 72 + q4 * 4);
        kd[0] = __floats2half2_rn(kq.x * rn, kq.y * rn);
        kd[1] = __floats2half2_rn(kq.z * rn, kq.w * rn);

        float4 vv = *(const float4*)(v + rowoff);
        int d0 = q4 * 4;
        VhH[(d0 + 0) * 136 + j] = __float2half_rn(vv.x);
        VhH[(d0 + 1) * 136 + j] = __float2half_rn(vv.y);
        VhH[(d0 + 2) * 136 + j] = __float2half_rn(vv.z);
        VhH[(d0 + 3) * 136 + j] = __float2half_rn(vv.w);
    }
    __syncthreads();

    int lane = tid & 31, warp = tid >> 5;
    int q = lane & 3, l4 = lane >> 2;
    int R0 = warp * 16 + l4;          // thread's rows: R0 and R0+8

    // LDSM lane addressing
    int rA  = warp * 16 + (lane & 15);            // A rows
    int hiA = (lane >> 4) * 16;                   // A k-offset (bytes)
    int rB  = (lane & 7) + ((lane >> 4) << 3);    // B row within 16-tile
    int hiB = ((lane >> 3) & 1) * 16;             // B k-offset (bytes)

    // ---- GEMM1: A-frags for all 4 k-blocks (k=16 each) ----
    uint32_t af[4][4];
    #pragma unroll
    for (int kb = 0; kb < 4; kb++)
        ldsm_x4(af[kb], sb + KH_OFF + rA * 144 + hiA + kb * 32);

    int tq0 = tkv[R0], tq1 = tkv[R0 + 8];
    float s0 = sQ[R0] * 0.125f, s1 = sQ[R0 + 8] * 0.125f;
    float sum0 = 0.f, sum1 = 0.f;
    __half2* AtH2 = (__half2*)(smem + AT_OFF);

    #pragma unroll
    for (int half = 0; half < 2; half++) {
        float c1[8][4];
        #pragma unroll
        for (int n = 0; n < 8; n++)
            #pragma unroll
            for (int e = 0; e < 4; e++) c1[n][e] = 0.f;

        #pragma unroll
        for (int np = 0; np < 4; np++) {
            uint32_t baddr = sb + KH_OFF + (half * 64 + np * 16 + rB) * 144 + hiB;
            #pragma unroll
            for (int kb = 0; kb < 4; kb++) {
                uint32_t bf[4];
                ldsm_x4(bf, baddr + kb * 32);
                mma16816(c1[2 * np],     af[kb], bf[0], bf[1]);
                mma16816(c1[2 * np + 1], af[kb], bf[2], bf[3]);
            }
        }

        // masks + exp (fixed bound s) + sums + fp16 store (unnormalized)
        #pragma unroll
        for (int n = 0; n < 8; n++) {
            int nt = half * 8 + n;
            int j0 = 8 * nt + 2 * q;
            int tk0 = tkv[j0], tk1 = tkv[j0 + 1];
            float e00 = (tq0 <= tk0) ? 0.f : __expf(s0 * (c1[n][0] - 1.f));
            float e01 = (tq0 <= tk1) ? 0.f : __expf(s0 * (c1[n][1] - 1.f));
            float e10 = (tq1 <= tk0) ? 0.f : __expf(s1 * (c1[n][2] - 1.f));
            float e11 = (tq1 <= tk1) ? 0.f : __expf(s1 * (c1[n][3] - 1.f));
            sum0 += e00 + e01;
            sum1 += e10 + e11;
            AtH2[R0 * 68 + nt * 4 + q]       = __floats2half2_rn(e00, e01);
            AtH2[(R0 + 8) * 68 + nt * 4 + q] = __floats2half2_rn(e10, e11);
        }
    }

    sum0 += __shfl_xor_sync(0xffffffffu, sum0, 1);
    sum0 += __shfl_xor_sync(0xffffffffu, sum0, 2);
    sum1 += __shfl_xor_sync(0xffffffffu, sum1, 1);
    sum1 += __shfl_xor_sync(0xffffffffu, sum1, 2);

    float inv0, inv1, lse0, lse1;
    __half* AtH = (__half*)(smem + AT_OFF);
    if (sum0 == 0.f) {   // all masked: self prob = 1 (self col index == row)
        if (q == 0) AtH[R0 * 136 + R0] = __float2half(1.0f);
        inv0 = 1.f; lse0 = -50000.f;
    } else { inv0 = 1.f / sum0; lse0 = s0 + __logf(sum0); }
    if (sum1 == 0.f) {
        if (q == 0) AtH[(R0 + 8) * 136 + (R0 + 8)] = __float2half(1.0f);
        inv1 = 1.f; lse1 = -50000.f;
    } else { inv1 = 1.f / sum1; lse1 = s1 + __logf(sum1); }

    if (q == 0) {
        g_logits[(size_t)(b * HH + h) * SS + tq0] = lse0;
        g_logits[(size_t)(b * HH + h) * SS + tq1] = lse1;
    }
    __syncwarp();   // attn stores visible to this warp's ldmatrix

    // ---- GEMM2: D2 = attn(64x128) · V^T(128x64), 8 k-blocks ----
    float c2[8][4];
    #pragma unroll
    for (int n = 0; n < 8; n++)
        #pragma unroll
        for (int e = 0; e < 4; e++) c2[n][e] = 0.f;

    #pragma unroll
    for (int kb = 0; kb < 8; kb++) {
        uint32_t a2[4];
        ldsm_x4(a2, sb + AT_OFF + rA * 272 + hiA + kb * 32);
        #pragma unroll
        for (int np = 0; np < 4; np++) {
            uint32_t bf[4];
            ldsm_x4(bf, sb + VH_OFF + (np * 16 + rB) * 272 + hiB + kb * 32);
            mma16816(c2[2 * np],     a2, bf[0], bf[1]);
            mma16816(c2[2 * np + 1], a2, bf[2], bf[3]);
        }
    }

    // ---- normalize + scatter ----
    float* dst0 = &g_o[((size_t)(b * HH + h) * SS + tq0) * DD];
    float* dst1 = &g_o[((size_t)(b * HH + h) * SS + tq1) * DD];
    #pragma unroll
    for (int n = 0; n < 8; n++) {
        int col = 8 * n + 2 * q;
        *(float2*)(dst0 + col) = make_float2(c2[n][0] * inv0, c2[n][1] * inv0);
        *(float2*)(dst1 + col) = make_float2(c2[n][2] * inv1, c2[n][3] * inv1);
    }
}

// =====================================================================
// Kernel 4: combine hash rounds (unchanged)
// =====================================================================
__global__ void __launch_bounds__(256) k_combine(float* __restrict__ out) {
    int gid = blockIdx.x * 256 + threadIdx.x;
    int token = gid >> 2, q = gid & 3;
    int b = token >> 12, t = token & 4095;

    float l[HH];
    #pragma unroll
    for (int h = 0; h < HH; h++)
        l[h] = g_logits[(size_t)(b * HH + h) * SS + t];
    float m = l[0];
    #pragma unroll
    for (int h = 1; h < HH; h++) m = fmaxf(m, l[h]);
    float w[HH]; float sum = 0.f;
    #pragma unroll
    for (int h = 0; h < HH; h++) { w[h] = expf(l[h] - m); sum += w[h]; }
    float inv = 1.0f / sum;

    float4 acc[4];
    #pragma unroll
    for (int k = 0; k < 4; k++) acc[k] = make_float4(0.f, 0.f, 0.f, 0.f);
    #pragma unroll
    for (int h = 0; h < HH; h++) {
        const float4* src =
            (const float4*)&g_o[((size_t)(b * HH + h) * SS + t) * DD + q * 16];
        float wh = w[h] * inv;
        #pragma unroll
        for (int k = 0; k < 4; k++) {
            float4 x = src[k];
            acc[k].x += x.x * wh; acc[k].y += x.y * wh;
            acc[k].z += x.z * wh; acc[k].w += x.w * wh;
        }
    }
    float4* dst = (float4*)(out + ((size_t)b * SS + t) * DD + q * 16);
    #pragma unroll
    for (int k = 0; k < 4; k++) dst[k] = acc[k];
}

// =====================================================================
extern "C" void kernel_launch(void* const* d_in, const int* in_sizes, int n_in,
                              void* d_out, int out_size) {
    const float* qk  = (const float*)d_in[0];
    const float* v   = (const float*)d_in[1];
    const float* rot = (const float*)d_in[2];
    float* out = (float*)d_out;

    const int smem1 = 64 * 66 * 4 + 64 * 130 * 8;   // 83456 B
    const int smem3 = SMEM3_SZ;                     // 54016 B -> 4 CTAs/SM
    cudaFuncSetAttribute(k_hash, cudaFuncAttributeMaxDynamicSharedMemorySize, smem1);
    cudaFuncSetAttribute(k_attn, cudaFuncAttributeMaxDynamicSharedMemorySize, smem3);

    k_hash<<<BB * TILES_PER_B, 512, smem1>>>(qk, rot);
    k_sort<<<BB * HH, 256>>>();
    k_probe<<<1, 32>>>();   // keeps ncu skip-5 capture on k_attn
    k_attn<<<BB * CPB, 128, smem3>>>(qk, v);
    k_combine<<<BB * SS * 4 / 256, 256>>>(out);
}